// round 14
// baseline (speedup 1.0000x reference)
#include <cuda_runtime.h>
#include <cuda_bf16.h>
#include <cstdint>

// Problem dims
#define BATCH 64
#define N1    1152
#define PDIM  8
#define N2    128
#define DDIM  16
#define KX    (N1*PDIM)          // 9216
#define BI    (BATCH*N1)         // 73728
#define EPSF  1.1920929e-7f

// ---- tiling (scalar kernels k2/k4p) ----
#define SLICES 9
#define ISL    (N1/SLICES)       // 128 i's per slice
#define IL     8                 // i's per smem tile
#define TILES  (ISL/IL)          // 16
#define NW     4                 // n's per CTA
#define NBLK   (N2/NW)           // 32
#define XROW   68                // padded x row
#define WS_F   (NW*IL*128)       // 4096 floats  (layout [il][nn][128])
#define XS_F   (BATCH*XROW)      // 4352 floats
#define STAGE_F (WS_F+XS_F)      // 8448 floats = 33 KB
#define SM_MAIN (2*STAGE_F*4)    // 67584 B
#define V0_F   (NW*DDIM*BATCH)   // 4096 floats
#define SM_K2  (SM_MAIN + V0_F*4) // 83968 B
#define LANE_BYTES  4096u

// ---- k1 mma.sync kernel ----
#define K1_NB     8              // n's per CTA -> M = 8*16 = 128 rows
#define K1_NBLK   (N2/K1_NB)     // 16
#define K1_TILES  16             // 128 i per slice / 8
#define K1_WST_F  8192           // fp32 stage: [il8][nn8][128]
#define K1_XST_F  (64*68)        // fp32 stage: [b][68]
#define K1_STG_F  (K1_WST_F+K1_XST_F)   // 12544 floats = 50176 B
// byte offsets in dynamic smem
#define K1_ST0    0u
#define K1_ST1    50176u
#define K1_WHI    100352u        // bf16 [128 rows][72]  = 18432 B
#define K1_WLO    118784u
#define K1_XHI    137216u        // bf16 [64 rows][72]   = 9216 B
#define K1_XLO    146432u
#define K1_SMEM   155648u
#define K1_LANE_TX 6144u         // per TMA lane: 4096 W + 8*256 x

typedef unsigned long long ull;

// ---------------- scratch (device globals; no allocations) ----------------
__device__ float g_raw[(size_t)N2 * N1 * BATCH];             // [n][i][b]; k3 converts to c in-place
__device__ float g_part[(size_t)SLICES * N2 * BATCH * DDIM]; // [s][n][b][d]

// ---------------- packed f32x2 helpers ----------------
__device__ __forceinline__ ull ffma2(ull a, ull b, ull c) {
    ull d;
    asm("fma.rn.f32x2 %0, %1, %2, %3;" : "=l"(d) : "l"(a), "l"(b), "l"(c));
    return d;
}
__device__ __forceinline__ ull fmul2(ull a, ull b) {
    ull d;
    asm("mul.rn.f32x2 %0, %1, %2;" : "=l"(d) : "l"(a), "l"(b));
    return d;
}
__device__ __forceinline__ ull pack2(float lo, float hi) {
    ull r;
    asm("mov.b64 %0, {%1, %2};" : "=l"(r) : "f"(lo), "f"(hi));
    return r;
}
__device__ __forceinline__ float hadd2(ull v) {
    float lo, hi;
    asm("mov.b64 {%0, %1}, %2;" : "=f"(lo), "=f"(hi) : "l"(v));
    return lo + hi;
}

// ---------------- bulk-async (TMA) + mbarrier helpers ----------------
__device__ __forceinline__ void mbar_init(uint32_t mbar, uint32_t count) {
    asm volatile("mbarrier.init.shared.b64 [%0], %1;" :: "r"(mbar), "r"(count) : "memory");
}
__device__ __forceinline__ void mbar_arrive_tx(uint32_t mbar, uint32_t bytes) {
    asm volatile("mbarrier.arrive.expect_tx.shared.b64 _, [%0], %1;"
                 :: "r"(mbar), "r"(bytes) : "memory");
}
__device__ __forceinline__ void mbar_wait(uint32_t mbar, uint32_t parity) {
    asm volatile(
        "{\n\t.reg .pred P;\n\t"
        "WL_%=:\n\t"
        "mbarrier.try_wait.parity.shared.b64 P, [%0], %1;\n\t"
        "@!P bra WL_%=;\n\t}"
        :: "r"(mbar), "r"(parity) : "memory");
}
__device__ __forceinline__ void cpbulk(uint32_t dst, const float* src,
                                       uint32_t bytes, uint32_t mbar) {
    asm volatile(
        "cp.async.bulk.shared::cta.global.mbarrier::complete_tx::bytes [%0], [%1], %2, [%3];"
        :: "r"(dst), "l"(src), "r"(bytes), "r"(mbar) : "memory");
}

// ---------------- mma.sync (baseline PTX, works on compute_103) ----------
__device__ __forceinline__ void mma_bf16(float* c, uint32_t a0, uint32_t a1,
                                         uint32_t b0) {
    asm volatile(
        "mma.sync.aligned.m16n8k8.row.col.f32.bf16.bf16.f32 "
        "{%0,%1,%2,%3}, {%4,%5}, {%6}, {%0,%1,%2,%3};"
        : "+f"(c[0]), "+f"(c[1]), "+f"(c[2]), "+f"(c[3])
        : "r"(a0), "r"(a1), "r"(b0));
}

// ---------------- bf16 split helper: hi + residual packed pairs ----------
__device__ __forceinline__ void bf16_split_pair(float f0, float f1,
                                                uint32_t& hi, uint32_t& lo) {
    __nv_bfloat16 h0 = __float2bfloat16(f0), h1 = __float2bfloat16(f1);
    hi = ((uint32_t)__bfloat16_as_ushort(h1) << 16) | (uint32_t)__bfloat16_as_ushort(h0);
    float r0 = f0 - __bfloat162float(h0), r1 = f1 - __bfloat162float(h1);
    __nv_bfloat16 l0 = __float2bfloat16(r0), l1 = __float2bfloat16(r1);
    lo = ((uint32_t)__bfloat16_as_ushort(l1) << 16) | (uint32_t)__bfloat16_as_ushort(l0);
}

// =====================================================================
// K1 via mma.sync: per CTA (8 n's, 128-i slice):
// D[row=(nn*16+d) 128, col=b 64] = sum_{il,p} W[i,n,d,p] * x[b,i,p]
// bf16 2-way split, 3 passes (hh, lo*hi, hi*lo), fp32 accumulators.
// Warp w owns rows [w*16, w*16+16) (= nn=w), all 64 b columns.
// =====================================================================
__global__ void __launch_bounds__(256) cap_k1m(const float* __restrict__ x,
                                               const float* __restrict__ W) {
    extern __shared__ float smf[];
    __shared__ __align__(8) ull mbars[2];
    const uint32_t sb = (uint32_t)__cvta_generic_to_shared(smf);
    const int n0 = blockIdx.x * K1_NB;
    const int s  = blockIdx.y;
    const int ib = s * ISL;
    const int t = threadIdx.x, w = t >> 5, lane = t & 31;
    const uint32_t mb[2] = { (uint32_t)__cvta_generic_to_shared(&mbars[0]),
                             (uint32_t)__cvta_generic_to_shared(&mbars[1]) };

    if (t == 0) { mbar_init(mb[0], 8); mbar_init(mb[1], 8); }
    __syncthreads();

    // TMA for tile tt into fp32 stage (tt&1)
    auto tma_tile = [&](int tt) {
        if (t < 8) {
            const uint32_t buf = sb + ((tt & 1) ? K1_ST1 : K1_ST0);
            const uint32_t mbb = mb[tt & 1];
            const int i0 = ib + tt * IL;
            mbar_arrive_tx(mbb, K1_LANE_TX);
            cpbulk(buf + (uint32_t)t * 4096u,
                   W + (size_t)(i0 + t) * (N2 * 128) + (size_t)n0 * 128, 4096, mbb);
#pragma unroll
            for (int r = 0; r < 8; r++) {
                const int b = t * 8 + r;
                cpbulk(buf + K1_WST_F * 4 + (uint32_t)b * 272u,
                       x + (size_t)b * KX + i0 * PDIM, 256, mbb);
            }
        }
    };

    __nv_bfloat16* whi = (__nv_bfloat16*)((char*)smf + K1_WHI);
    __nv_bfloat16* wlo = (__nv_bfloat16*)((char*)smf + K1_WLO);
    __nv_bfloat16* xhi = (__nv_bfloat16*)((char*)smf + K1_XHI);
    __nv_bfloat16* xlo = (__nv_bfloat16*)((char*)smf + K1_XLO);
    const uint32_t* whi32 = (const uint32_t*)whi;
    const uint32_t* wlo32 = (const uint32_t*)wlo;
    const uint32_t* xhi32 = (const uint32_t*)xhi;
    const uint32_t* xlo32 = (const uint32_t*)xlo;

    float acc[8][4];
#pragma unroll
    for (int nt = 0; nt < 8; nt++)
#pragma unroll
        for (int e = 0; e < 4; e++) acc[nt][e] = 0.f;

    tma_tile(0);

    for (int tt = 0; tt < K1_TILES; tt++) {
        if (tt + 1 < K1_TILES) tma_tile(tt + 1);
        mbar_wait(mb[tt & 1], (tt >> 1) & 1);

        const float* wst = smf + ((tt & 1) ? (K1_ST1 / 4) : 0);
        const float* xst = wst + K1_WST_F;

        // ---- convert fp32 -> bf16 hi/lo (padded stride 72) ----
        // W: 8192 elems -> row = nn*16+d, col = il*8+p
        for (int idx = t; idx < 8192; idx += 256) {
            const int il = idx >> 10, nn = (idx >> 7) & 7, dp = idx & 127;
            const int row = nn * 16 + (dp >> 3);
            const int col = il * 8 + (dp & 7);
            const float f = wst[il * 1024 + nn * 128 + dp];
            __nv_bfloat16 h = __float2bfloat16(f);
            whi[row * 72 + col] = h;
            wlo[row * 72 + col] = __float2bfloat16(f - __bfloat162float(h));
        }
        // x: 4096 elems -> row = b, col = k
        for (int idx = t; idx < 4096; idx += 256) {
            const int b = idx >> 6, k = idx & 63;
            const float f = xst[b * 68 + k];
            __nv_bfloat16 h = __float2bfloat16(f);
            xhi[b * 72 + k] = h;
            xlo[b * 72 + k] = __float2bfloat16(f - __bfloat162float(h));
        }
        __syncthreads();   // bf16 tiles ready

        // ---- mma: warp w = rows w*16..w*16+15, 8 k-steps, 8 n-tiles ----
        const int r0 = w * 16 + (lane >> 2);
        const int kwo = lane & 3;
#pragma unroll
        for (int kk = 0; kk < 8; kk++) {
            const int kw = kk * 4 + kwo;            // 32-bit word index in k
            const uint32_t a0h = whi32[r0 * 36 + kw];
            const uint32_t a1h = whi32[(r0 + 8) * 36 + kw];
            const uint32_t a0l = wlo32[r0 * 36 + kw];
            const uint32_t a1l = wlo32[(r0 + 8) * 36 + kw];
#pragma unroll
            for (int nt = 0; nt < 8; nt++) {
                const int bcol = nt * 8 + (lane >> 2);
                const uint32_t bh = xhi32[bcol * 36 + kw];
                const uint32_t bl = xlo32[bcol * 36 + kw];
                mma_bf16(acc[nt], a0h, a1h, bh);
                mma_bf16(acc[nt], a0l, a1l, bh);
                mma_bf16(acc[nt], a0h, a1h, bl);
            }
        }
        __syncthreads();   // mma done; bf16 tiles may be overwritten
    }

    // ---- epilogue: write D to g_part[s][n0+w][b][d] ----
    {
        const int n = n0 + w;
        const int d0 = lane >> 2, d1 = d0 + 8;
        float* gp = &g_part[(((size_t)s * N2 + n) * BATCH) * DDIM];
#pragma unroll
        for (int nt = 0; nt < 8; nt++) {
            const int b = nt * 8 + (lane & 3) * 2;
            gp[(b)     * DDIM + d0] = acc[nt][0];
            gp[(b + 1) * DDIM + d0] = acc[nt][1];
            gp[(b)     * DDIM + d1] = acc[nt][2];
            gp[(b + 1) * DDIM + d1] = acc[nt][3];
        }
    }
}

// ---------------- scalar tile loader (k2/k4p, unchanged from R11) ----------
__device__ __forceinline__ void tile_load(uint32_t stage_s, uint32_t mbar,
                                          const float* __restrict__ x,
                                          const float* __restrict__ W,
                                          int n0, int i0, int t) {
    if (t < 8) {
        mbar_arrive_tx(mbar, LANE_BYTES);
        const int il = t;
        cpbulk(stage_s + (uint32_t)(il * NW * 128) * 4,
               W + (size_t)(i0 + il) * (N2 * DDIM * PDIM)
                 + (size_t)n0 * (DDIM * PDIM),
               2048, mbar);
        uint32_t xs_s = stage_s + WS_F * 4;
#pragma unroll
        for (int r = 0; r < 8; r++) {
            const int b = il * 8 + r;
            cpbulk(xs_s + (uint32_t)(b * XROW) * 4,
                   x + (size_t)b * KX + i0 * PDIM, 256, mbar);
        }
    }
}

// =====================================================================
// K2 (fused K1-reduce): v0 for 4 n's into smem [nn][d][b], then
// raw[n][i][b] = sum_p x[b,i,p] * ( sum_d v0[n,b,d] W[i,n,d,p] )
// =====================================================================
__global__ void __launch_bounds__(256, 2) cap_k2(const float* __restrict__ x,
                                                 const float* __restrict__ W) {
    extern __shared__ float sm[];
    __shared__ __align__(8) ull mbars[2];
    float* v0s = sm + 2 * STAGE_F;
    const int n0 = blockIdx.x * NW, s = blockIdx.y;
    const int t = threadIdx.x, w = t >> 5, lane = t & 31;
    const int b0 = lane, b1 = lane + 32;
    const int ib = s * ISL;
    const uint32_t sbase = (uint32_t)__cvta_generic_to_shared(sm);
    const uint32_t mb[2] = { (uint32_t)__cvta_generic_to_shared(&mbars[0]),
                             (uint32_t)__cvta_generic_to_shared(&mbars[1]) };

    if (t == 0) { mbar_init(mb[0], 8); mbar_init(mb[1], 8); }

    {
        int bb = t >> 2, dq = t & 3;
#pragma unroll
        for (int nn = 0; nn < NW; nn++) {
            float4 v = make_float4(0.f, 0.f, 0.f, 0.f);
            for (int sl = 0; sl < SLICES; sl++) {
                float4 p = *(const float4*)&g_part[(((size_t)sl * N2 + n0 + nn) * BATCH + bb) * DDIM + dq * 4];
                v.x += p.x; v.y += p.y; v.z += p.z; v.w += p.w;
            }
            *(float4*)&sm[(nn * BATCH + bb) * DDIM + dq * 4] = v;
        }
    }
    __syncthreads();
    {
        int nn = t >> 6, b = t & 63;
        float sv[16], sq = 0.f;
#pragma unroll
        for (int d = 0; d < 16; d++) {
            float v = sm[(nn * BATCH + b) * DDIM + d] * (1.f / 128.f);
            sv[d] = v; sq += v * v;
        }
        float f = sq / ((1.f + sq) * sqrtf(sq + EPSF));
        __syncthreads();
#pragma unroll
        for (int d = 0; d < 16; d++)
            v0s[(nn * DDIM + d) * BATCH + b] = f * sv[d];
    }
    __syncthreads();

    tile_load(sbase, mb[0], x, W, n0, ib, t);

    for (int tt = 0; tt < TILES; tt++) {
        mbar_wait(mb[tt & 1], (tt >> 1) & 1);
        __syncthreads();
        if (tt + 1 < TILES)
            tile_load(sbase + ((tt + 1) & 1) * STAGE_F * 4, mb[(tt + 1) & 1],
                      x, W, n0, ib + (tt + 1) * IL, t);

        const float* wsb = sm + (tt & 1) * STAGE_F;
        const float* xsb = wsb + WS_F;
        const int i = ib + tt * IL + w;
        ulonglong2 xA01 = *(const ulonglong2*)&xsb[b0 * XROW + w * 8];
        ulonglong2 xA23 = *(const ulonglong2*)&xsb[b0 * XROW + w * 8 + 4];
        ulonglong2 xB01 = *(const ulonglong2*)&xsb[b1 * XROW + w * 8];
        ulonglong2 xB23 = *(const ulonglong2*)&xsb[b1 * XROW + w * 8 + 4];

#pragma unroll
        for (int nn = 0; nn < NW; nn++) {
            const ulonglong2* wv = (const ulonglong2*)&wsb[(w * NW + nn) * 128];
            ull tA0 = 0, tA1 = 0, tA2 = 0, tA3 = 0;
            ull tB0 = 0, tB1 = 0, tB2 = 0, tB3 = 0;
#pragma unroll
            for (int d = 0; d < 16; d++) {
                float uA = v0s[(nn * DDIM + d) * BATCH + b0];
                float uB = v0s[(nn * DDIM + d) * BATCH + b1];
                ull u2A = pack2(uA, uA);
                ull u2B = pack2(uB, uB);
                ulonglong2 w01 = wv[2 * d], w23 = wv[2 * d + 1];
                tA0 = ffma2(u2A, w01.x, tA0);
                tA1 = ffma2(u2A, w01.y, tA1);
                tA2 = ffma2(u2A, w23.x, tA2);
                tA3 = ffma2(u2A, w23.y, tA3);
                tB0 = ffma2(u2B, w01.x, tB0);
                tB1 = ffma2(u2B, w01.y, tB1);
                tB2 = ffma2(u2B, w23.x, tB2);
                tB3 = ffma2(u2B, w23.y, tB3);
            }
            ull rA = fmul2(xA01.x, tA0);
            rA = ffma2(xA01.y, tA1, rA);
            rA = ffma2(xA23.x, tA2, rA);
            rA = ffma2(xA23.y, tA3, rA);
            ull rB = fmul2(xB01.x, tB0);
            rB = ffma2(xB01.y, tB1, rB);
            rB = ffma2(xB23.x, tB2, rB);
            rB = ffma2(xB23.y, tB3, rB);
            g_raw[(size_t)(n0 + nn) * BI + (size_t)i * BATCH + b0] = hadd2(rA);
            g_raw[(size_t)(n0 + nn) * BI + (size_t)i * BATCH + b1] = hadd2(rB);
        }
    }
}

// =====================================================================
// K3: per (b,i): s = sum_n exp(raw); then IN-PLACE raw <- c = exp(raw)/s
// =====================================================================
__global__ void __launch_bounds__(256) cap_k3() {
    const int j = blockIdx.x * 256 + threadIdx.x;
    float s0 = 0.f, s1 = 0.f;
#pragma unroll 8
    for (int n = 0; n < N2; n += 2) {
        s0 += __expf(g_raw[(size_t)n * BI + j]);
        s1 += __expf(g_raw[(size_t)(n + 1) * BI + j]);
    }
    const float inv = 1.f / (s0 + s1);
#pragma unroll 8
    for (int n = 0; n < N2; n++) {
        float r = g_raw[(size_t)n * BI + j];
        g_raw[(size_t)n * BI + j] = __expf(r) * inv;
    }
}

// =====================================================================
// K4 partial: part[s][n0+nn][b][d] = sum_{i in slice} c * pred
// =====================================================================
__global__ void __launch_bounds__(256, 2) cap_k4p(const float* __restrict__ x,
                                                  const float* __restrict__ W) {
    extern __shared__ float sm[];
    __shared__ __align__(8) ull mbars[2];
    const int n0 = blockIdx.x * NW, s = blockIdx.y;
    const int t = threadIdx.x, w = t >> 5, lane = t & 31;
    const int dq = w & 3, ilh = w >> 2;
    const int b0 = lane, b1 = lane + 32;
    const int ib = s * ISL;
    const uint32_t sbase = (uint32_t)__cvta_generic_to_shared(sm);
    const uint32_t mb[2] = { (uint32_t)__cvta_generic_to_shared(&mbars[0]),
                             (uint32_t)__cvta_generic_to_shared(&mbars[1]) };

    if (t == 0) { mbar_init(mb[0], 8); mbar_init(mb[1], 8); }
    __syncthreads();

    ull accA[NW][4], accB[NW][4];
#pragma unroll
    for (int nn = 0; nn < NW; nn++)
#pragma unroll
        for (int e = 0; e < 4; e++) { accA[nn][e] = 0ULL; accB[nn][e] = 0ULL; }

    tile_load(sbase, mb[0], x, W, n0, ib, t);

    for (int tt = 0; tt < TILES; tt++) {
        mbar_wait(mb[tt & 1], (tt >> 1) & 1);
        __syncthreads();
        if (tt + 1 < TILES)
            tile_load(sbase + ((tt + 1) & 1) * STAGE_F * 4, mb[(tt + 1) & 1],
                      x, W, n0, ib + (tt + 1) * IL, t);

        const float* wsb = sm + (tt & 1) * STAGE_F;
        const float* xsb = wsb + WS_F;
#pragma unroll
        for (int ii = 0; ii < 4; ii++) {
            const int il = ilh * 4 + ii;
            const int i = ib + tt * IL + il;
            ulonglong2 xA01 = *(const ulonglong2*)&xsb[b0 * XROW + il * 8];
            ulonglong2 xA23 = *(const ulonglong2*)&xsb[b0 * XROW + il * 8 + 4];
            ulonglong2 xB01 = *(const ulonglong2*)&xsb[b1 * XROW + il * 8];
            ulonglong2 xB23 = *(const ulonglong2*)&xsb[b1 * XROW + il * 8 + 4];
#pragma unroll
            for (int nn = 0; nn < NW; nn++) {
                float cA = g_raw[(size_t)(n0 + nn) * BI + (size_t)i * BATCH + b0];
                float cB = g_raw[(size_t)(n0 + nn) * BI + (size_t)i * BATCH + b1];
                ull c2A = pack2(cA, cA);
                ull c2B = pack2(cB, cB);
                ull xa0 = fmul2(c2A, xA01.x), xa1 = fmul2(c2A, xA01.y);
                ull xa2 = fmul2(c2A, xA23.x), xa3 = fmul2(c2A, xA23.y);
                ull xb0 = fmul2(c2B, xB01.x), xb1 = fmul2(c2B, xB01.y);
                ull xb2 = fmul2(c2B, xB23.x), xb3 = fmul2(c2B, xB23.y);
                const ulonglong2* wv =
                    (const ulonglong2*)&wsb[(il * NW + nn) * 128 + dq * 32];
#pragma unroll
                for (int e = 0; e < 4; e++) {
                    ulonglong2 w01 = wv[2 * e], w23 = wv[2 * e + 1];
                    accA[nn][e] = ffma2(w01.x, xa0, accA[nn][e]);
                    accA[nn][e] = ffma2(w01.y, xa1, accA[nn][e]);
                    accA[nn][e] = ffma2(w23.x, xa2, accA[nn][e]);
                    accA[nn][e] = ffma2(w23.y, xa3, accA[nn][e]);
                    accB[nn][e] = ffma2(w01.x, xb0, accB[nn][e]);
                    accB[nn][e] = ffma2(w01.y, xb1, accB[nn][e]);
                    accB[nn][e] = ffma2(w23.x, xb2, accB[nn][e]);
                    accB[nn][e] = ffma2(w23.y, xb3, accB[nn][e]);
                }
            }
        }
    }

    __syncthreads();
    float* red = sm;
#pragma unroll
    for (int nn = 0; nn < NW; nn++)
#pragma unroll
        for (int e = 0; e < 4; e++) {
            red[w * 1024 + b0 * 16 + nn * 4 + e] = hadd2(accA[nn][e]);
            red[w * 1024 + b1 * 16 + nn * 4 + e] = hadd2(accB[nn][e]);
        }
    __syncthreads();
    {
        int bb = t >> 2, q = t & 3;
#pragma unroll
        for (int nn = 0; nn < NW; nn++) {
            float v[4];
#pragma unroll
            for (int e = 0; e < 4; e++)
                v[e] = red[(0 * 4 + q) * 1024 + bb * 16 + nn * 4 + e]
                     + red[(1 * 4 + q) * 1024 + bb * 16 + nn * 4 + e];
            *(float4*)&g_part[(((size_t)s * N2 + n0 + nn) * BATCH + bb) * DDIM + q * 4] =
                make_float4(v[0], v[1], v[2], v[3]);
        }
    }
}

// =====================================================================
// K4 reduce: out[b][n][d] = squash_d( sum_s part[s][n][b][d] )
// =====================================================================
__global__ void __launch_bounds__(64) cap_k4r(float* __restrict__ out) {
    const int n = blockIdx.x, b = threadIdx.x;
    float sv[16];
#pragma unroll
    for (int d = 0; d < 16; d++) sv[d] = 0.f;
    for (int sl = 0; sl < SLICES; sl++) {
        const float4* p = (const float4*)&g_part[(((size_t)sl * N2 + n) * BATCH + b) * DDIM];
#pragma unroll
        for (int q = 0; q < 4; q++) {
            float4 v = p[q];
            sv[4 * q + 0] += v.x; sv[4 * q + 1] += v.y;
            sv[4 * q + 2] += v.z; sv[4 * q + 3] += v.w;
        }
    }
    float sq = 0.f;
#pragma unroll
    for (int d = 0; d < 16; d++) sq += sv[d] * sv[d];
    float f = sq / ((1.f + sq) * sqrtf(sq + EPSF));
    float4* o = (float4*)&out[((size_t)b * N2 + n) * DDIM];
#pragma unroll
    for (int q = 0; q < 4; q++)
        o[q] = make_float4(f * sv[4 * q], f * sv[4 * q + 1],
                           f * sv[4 * q + 2], f * sv[4 * q + 3]);
}

// =====================================================================
extern "C" void kernel_launch(void* const* d_in, const int* in_sizes, int n_in,
                              void* d_out, int out_size) {
    const float* x = (const float*)d_in[0];
    const float* W = (const float*)d_in[1];
    if (n_in >= 2 && in_sizes[0] > in_sizes[1]) {
        const float* tmp = x; x = W; W = tmp;
    }
    float* out = (float*)d_out;

    cudaFuncSetAttribute(cap_k1m, cudaFuncAttributeMaxDynamicSharedMemorySize, K1_SMEM);
    cudaFuncSetAttribute(cap_k2,  cudaFuncAttributeMaxDynamicSharedMemorySize, SM_K2);
    cudaFuncSetAttribute(cap_k4p, cudaFuncAttributeMaxDynamicSharedMemorySize, SM_MAIN);

    dim3 g1(K1_NBLK, SLICES);
    dim3 g(NBLK, SLICES);
    cap_k1m<<<g1, 256, K1_SMEM>>>(x, W);
    cap_k2 <<<g, 256, SM_K2 >>>(x, W);
    cap_k3 <<<BI / 256, 256>>>();
    cap_k4p<<<g, 256, SM_MAIN>>>(x, W);
    cap_k4r<<<N2, 64>>>(out);
}

// round 16
// speedup vs baseline: 1.1043x; 1.1043x over previous
#include <cuda_runtime.h>
#include <cstdint>

// Problem dims
#define BATCH 64
#define N1    1152
#define PDIM  8
#define N2    128
#define DDIM  16
#define KX    (N1*PDIM)          // 9216
#define BI    (BATCH*N1)         // 73728
#define EPSF  1.1920929e-7f

// ---- tiling ----
#define SLICES 9
#define ISL    (N1/SLICES)       // 128 i's per slice
#define IL     8                 // i's per smem tile
#define TILES  (ISL/IL)          // 16
#define NW     4                 // n's per CTA
#define NBLK   (N2/NW)           // 32
#define XROW   68                // padded x row
#define WS_F   (NW*IL*128)       // 4096 floats  (layout [il][nn][128])
#define XS_F   (BATCH*XROW)      // 4352 floats
#define STAGE_F (WS_F+XS_F)      // 8448 floats = 33 KB
#define SM_MAIN (2*STAGE_F*4)    // 67584 B
#define V0_F   (NW*DDIM*BATCH)   // 4096 floats
#define SM_K2  (SM_MAIN + V0_F*4) // 83968 B
#define LANE_BYTES  4096u
// k4p stage: W + x + c tile ([nn4][il8][b64] fp32 = 8 KB)
#define C_F     2048
#define STAGE4_F (STAGE_F + C_F)  // 10496 floats = 41 KB
#define SM_K4   (2*STAGE4_F*4)    // 83968 B

typedef unsigned long long ull;

// ---------------- scratch (device globals; no allocations) ----------------
__device__ float g_raw[(size_t)N2 * N1 * BATCH];             // [n][i][b]; k3 converts to c in-place
__device__ float g_part[(size_t)SLICES * N2 * BATCH * DDIM]; // [s][n][b][d]

// ---------------- packed f32x2 helpers ----------------
__device__ __forceinline__ ull ffma2(ull a, ull b, ull c) {
    ull d;
    asm("fma.rn.f32x2 %0, %1, %2, %3;" : "=l"(d) : "l"(a), "l"(b), "l"(c));
    return d;
}
__device__ __forceinline__ ull fmul2(ull a, ull b) {
    ull d;
    asm("mul.rn.f32x2 %0, %1, %2;" : "=l"(d) : "l"(a), "l"(b));
    return d;
}
__device__ __forceinline__ ull pack2(float lo, float hi) {
    ull r;
    asm("mov.b64 %0, {%1, %2};" : "=l"(r) : "f"(lo), "f"(hi));
    return r;
}
__device__ __forceinline__ float hadd2(ull v) {
    float lo, hi;
    asm("mov.b64 {%0, %1}, %2;" : "=f"(lo), "=f"(hi) : "l"(v));
    return lo + hi;
}

// ---------------- bulk-async (TMA) + mbarrier helpers ----------------
__device__ __forceinline__ void mbar_init(uint32_t mbar, uint32_t count) {
    asm volatile("mbarrier.init.shared.b64 [%0], %1;" :: "r"(mbar), "r"(count) : "memory");
}
__device__ __forceinline__ void mbar_arrive_tx(uint32_t mbar, uint32_t bytes) {
    asm volatile("mbarrier.arrive.expect_tx.shared.b64 _, [%0], %1;"
                 :: "r"(mbar), "r"(bytes) : "memory");
}
__device__ __forceinline__ void mbar_wait(uint32_t mbar, uint32_t parity) {
    asm volatile(
        "{\n\t.reg .pred P;\n\t"
        "WL_%=:\n\t"
        "mbarrier.try_wait.parity.shared.b64 P, [%0], %1;\n\t"
        "@!P bra WL_%=;\n\t}"
        :: "r"(mbar), "r"(parity) : "memory");
}
__device__ __forceinline__ void cpbulk(uint32_t dst, const float* src,
                                       uint32_t bytes, uint32_t mbar) {
    asm volatile(
        "cp.async.bulk.shared::cta.global.mbarrier::complete_tx::bytes [%0], [%1], %2, [%3];"
        :: "r"(dst), "l"(src), "r"(bytes), "r"(mbar) : "memory");
}

// ---------------- tile loader (W + x), 8 producer lanes ----------------
__device__ __forceinline__ void tile_load(uint32_t stage_s, uint32_t mbar,
                                          const float* __restrict__ x,
                                          const float* __restrict__ W,
                                          int n0, int i0, int t) {
    if (t < 8) {
        mbar_arrive_tx(mbar, LANE_BYTES);
        const int il = t;
        cpbulk(stage_s + (uint32_t)(il * NW * 128) * 4,
               W + (size_t)(i0 + il) * (N2 * DDIM * PDIM)
                 + (size_t)n0 * (DDIM * PDIM),
               2048, mbar);
        uint32_t xs_s = stage_s + WS_F * 4;
#pragma unroll
        for (int r = 0; r < 8; r++) {
            const int b = il * 8 + r;
            cpbulk(xs_s + (uint32_t)(b * XROW) * 4,
                   x + (size_t)b * KX + i0 * PDIM, 256, mbar);
        }
    }
}

// ---------------- tile loader with c prefetch (k4p) ----------------
// c region: stage + STAGE_F floats, layout [nn][il][b] (2 KB contiguous per nn)
__device__ __forceinline__ void tile_load_c(uint32_t stage_s, uint32_t mbar,
                                            const float* __restrict__ x,
                                            const float* __restrict__ W,
                                            int n0, int i0, int t) {
    if (t < 8) {
        mbar_arrive_tx(mbar, (t < 4) ? (LANE_BYTES + 2048u) : LANE_BYTES);
        const int il = t;
        cpbulk(stage_s + (uint32_t)(il * NW * 128) * 4,
               W + (size_t)(i0 + il) * (N2 * DDIM * PDIM)
                 + (size_t)n0 * (DDIM * PDIM),
               2048, mbar);
        uint32_t xs_s = stage_s + WS_F * 4;
#pragma unroll
        for (int r = 0; r < 8; r++) {
            const int b = il * 8 + r;
            cpbulk(xs_s + (uint32_t)(b * XROW) * 4,
                   x + (size_t)b * KX + i0 * PDIM, 256, mbar);
        }
        if (t < 4) {
            // c[nn=t]: g_raw rows [n0+t][i0..i0+7][0..63] = 512 floats contiguous
            cpbulk(stage_s + (uint32_t)(STAGE_F + t * 512) * 4,
                   &g_raw[(size_t)(n0 + t) * BI + (size_t)i0 * BATCH], 2048, mbar);
        }
    }
}

// =====================================================================
// K1 partial: part[s][n0+nn][b][d] = sum_{i in slice, p} W[i,n,d,p] x[b,i,p]
// warp w: dq = w&3 (d = dq*4+e), ilh = w>>2 (il = ilh*4+ii); b0=lane,b1=lane+32
// =====================================================================
__global__ void __launch_bounds__(256, 2) cap_k1p(const float* __restrict__ x,
                                                  const float* __restrict__ W) {
    extern __shared__ float sm[];
    __shared__ __align__(8) ull mbars[2];
    const int n0 = blockIdx.x * NW, s = blockIdx.y;
    const int t = threadIdx.x, w = t >> 5, lane = t & 31;
    const int dq = w & 3, ilh = w >> 2;
    const int b0 = lane, b1 = lane + 32;
    const int ib = s * ISL;
    const uint32_t sbase = (uint32_t)__cvta_generic_to_shared(sm);
    const uint32_t mb[2] = { (uint32_t)__cvta_generic_to_shared(&mbars[0]),
                             (uint32_t)__cvta_generic_to_shared(&mbars[1]) };

    if (t == 0) { mbar_init(mb[0], 8); mbar_init(mb[1], 8); }
    __syncthreads();

    ull accA[NW][4], accB[NW][4];
#pragma unroll
    for (int nn = 0; nn < NW; nn++)
#pragma unroll
        for (int e = 0; e < 4; e++) { accA[nn][e] = 0ULL; accB[nn][e] = 0ULL; }

    tile_load(sbase, mb[0], x, W, n0, ib, t);

    for (int tt = 0; tt < TILES; tt++) {
        mbar_wait(mb[tt & 1], (tt >> 1) & 1);
        __syncthreads();
        if (tt + 1 < TILES)
            tile_load(sbase + ((tt + 1) & 1) * STAGE_F * 4, mb[(tt + 1) & 1],
                      x, W, n0, ib + (tt + 1) * IL, t);

        const float* wsb = sm + (tt & 1) * STAGE_F;
        const float* xsb = wsb + WS_F;
#pragma unroll
        for (int ii = 0; ii < 4; ii++) {
            const int il = ilh * 4 + ii;
            ulonglong2 xA01 = *(const ulonglong2*)&xsb[b0 * XROW + il * 8];
            ulonglong2 xA23 = *(const ulonglong2*)&xsb[b0 * XROW + il * 8 + 4];
            ulonglong2 xB01 = *(const ulonglong2*)&xsb[b1 * XROW + il * 8];
            ulonglong2 xB23 = *(const ulonglong2*)&xsb[b1 * XROW + il * 8 + 4];
#pragma unroll
            for (int nn = 0; nn < NW; nn++) {
                const ulonglong2* wv =
                    (const ulonglong2*)&wsb[(il * NW + nn) * 128 + dq * 32];
#pragma unroll
                for (int e = 0; e < 4; e++) {
                    ulonglong2 w01 = wv[2 * e], w23 = wv[2 * e + 1];
                    accA[nn][e] = ffma2(w01.x, xA01.x, accA[nn][e]);
                    accA[nn][e] = ffma2(w01.y, xA01.y, accA[nn][e]);
                    accA[nn][e] = ffma2(w23.x, xA23.x, accA[nn][e]);
                    accA[nn][e] = ffma2(w23.y, xA23.y, accA[nn][e]);
                    accB[nn][e] = ffma2(w01.x, xB01.x, accB[nn][e]);
                    accB[nn][e] = ffma2(w01.y, xB01.y, accB[nn][e]);
                    accB[nn][e] = ffma2(w23.x, xB23.x, accB[nn][e]);
                    accB[nn][e] = ffma2(w23.y, xB23.y, accB[nn][e]);
                }
            }
        }
    }

    __syncthreads();
    float* red = sm;     // [8 w][64 b][16 nn*4+e] = 8192 f
#pragma unroll
    for (int nn = 0; nn < NW; nn++)
#pragma unroll
        for (int e = 0; e < 4; e++) {
            red[w * 1024 + b0 * 16 + nn * 4 + e] = hadd2(accA[nn][e]);
            red[w * 1024 + b1 * 16 + nn * 4 + e] = hadd2(accB[nn][e]);
        }
    __syncthreads();
    {
        int bb = t >> 2, q = t & 3;
#pragma unroll
        for (int nn = 0; nn < NW; nn++) {
            float v[4];
#pragma unroll
            for (int e = 0; e < 4; e++)
                v[e] = red[(0 * 4 + q) * 1024 + bb * 16 + nn * 4 + e]
                     + red[(1 * 4 + q) * 1024 + bb * 16 + nn * 4 + e];
            *(float4*)&g_part[(((size_t)s * N2 + n0 + nn) * BATCH + bb) * DDIM + q * 4] =
                make_float4(v[0], v[1], v[2], v[3]);
        }
    }
}

// =====================================================================
// K2 (fused K1-reduce): v0 for 4 n's into smem [nn][d][b], then
// raw[n][i][b] = sum_p x[b,i,p] * ( sum_d v0[n,b,d] W[i,n,d,p] )
// =====================================================================
__global__ void __launch_bounds__(256, 2) cap_k2(const float* __restrict__ x,
                                                 const float* __restrict__ W) {
    extern __shared__ float sm[];
    __shared__ __align__(8) ull mbars[2];
    float* v0s = sm + 2 * STAGE_F;
    const int n0 = blockIdx.x * NW, s = blockIdx.y;
    const int t = threadIdx.x, w = t >> 5, lane = t & 31;
    const int b0 = lane, b1 = lane + 32;
    const int ib = s * ISL;
    const uint32_t sbase = (uint32_t)__cvta_generic_to_shared(sm);
    const uint32_t mb[2] = { (uint32_t)__cvta_generic_to_shared(&mbars[0]),
                             (uint32_t)__cvta_generic_to_shared(&mbars[1]) };

    if (t == 0) { mbar_init(mb[0], 8); mbar_init(mb[1], 8); }

    {
        int bb = t >> 2, dq = t & 3;
#pragma unroll
        for (int nn = 0; nn < NW; nn++) {
            float4 v = make_float4(0.f, 0.f, 0.f, 0.f);
            for (int sl = 0; sl < SLICES; sl++) {
                float4 p = *(const float4*)&g_part[(((size_t)sl * N2 + n0 + nn) * BATCH + bb) * DDIM + dq * 4];
                v.x += p.x; v.y += p.y; v.z += p.z; v.w += p.w;
            }
            *(float4*)&sm[(nn * BATCH + bb) * DDIM + dq * 4] = v;
        }
    }
    __syncthreads();
    {
        int nn = t >> 6, b = t & 63;
        float sv[16], sq = 0.f;
#pragma unroll
        for (int d = 0; d < 16; d++) {
            float v = sm[(nn * BATCH + b) * DDIM + d] * (1.f / 128.f);
            sv[d] = v; sq += v * v;
        }
        float f = sq / ((1.f + sq) * sqrtf(sq + EPSF));
        __syncthreads();
#pragma unroll
        for (int d = 0; d < 16; d++)
            v0s[(nn * DDIM + d) * BATCH + b] = f * sv[d];
    }
    __syncthreads();

    tile_load(sbase, mb[0], x, W, n0, ib, t);

    for (int tt = 0; tt < TILES; tt++) {
        mbar_wait(mb[tt & 1], (tt >> 1) & 1);
        __syncthreads();
        if (tt + 1 < TILES)
            tile_load(sbase + ((tt + 1) & 1) * STAGE_F * 4, mb[(tt + 1) & 1],
                      x, W, n0, ib + (tt + 1) * IL, t);

        const float* wsb = sm + (tt & 1) * STAGE_F;
        const float* xsb = wsb + WS_F;
        const int i = ib + tt * IL + w;
        ulonglong2 xA01 = *(const ulonglong2*)&xsb[b0 * XROW + w * 8];
        ulonglong2 xA23 = *(const ulonglong2*)&xsb[b0 * XROW + w * 8 + 4];
        ulonglong2 xB01 = *(const ulonglong2*)&xsb[b1 * XROW + w * 8];
        ulonglong2 xB23 = *(const ulonglong2*)&xsb[b1 * XROW + w * 8 + 4];

#pragma unroll
        for (int nn = 0; nn < NW; nn++) {
            const ulonglong2* wv = (const ulonglong2*)&wsb[(w * NW + nn) * 128];
            ull tA0 = 0, tA1 = 0, tA2 = 0, tA3 = 0;
            ull tB0 = 0, tB1 = 0, tB2 = 0, tB3 = 0;
#pragma unroll
            for (int d = 0; d < 16; d++) {
                float uA = v0s[(nn * DDIM + d) * BATCH + b0];
                float uB = v0s[(nn * DDIM + d) * BATCH + b1];
                ull u2A = pack2(uA, uA);
                ull u2B = pack2(uB, uB);
                ulonglong2 w01 = wv[2 * d], w23 = wv[2 * d + 1];
                tA0 = ffma2(u2A, w01.x, tA0);
                tA1 = ffma2(u2A, w01.y, tA1);
                tA2 = ffma2(u2A, w23.x, tA2);
                tA3 = ffma2(u2A, w23.y, tA3);
                tB0 = ffma2(u2B, w01.x, tB0);
                tB1 = ffma2(u2B, w01.y, tB1);
                tB2 = ffma2(u2B, w23.x, tB2);
                tB3 = ffma2(u2B, w23.y, tB3);
            }
            ull rA = fmul2(xA01.x, tA0);
            rA = ffma2(xA01.y, tA1, rA);
            rA = ffma2(xA23.x, tA2, rA);
            rA = ffma2(xA23.y, tA3, rA);
            ull rB = fmul2(xB01.x, tB0);
            rB = ffma2(xB01.y, tB1, rB);
            rB = ffma2(xB23.x, tB2, rB);
            rB = ffma2(xB23.y, tB3, rB);
            g_raw[(size_t)(n0 + nn) * BI + (size_t)i * BATCH + b0] = hadd2(rA);
            g_raw[(size_t)(n0 + nn) * BI + (size_t)i * BATCH + b1] = hadd2(rB);
        }
    }
}

// =====================================================================
// K3: per (b,i): s = sum_n exp(raw); then IN-PLACE raw <- c = exp(raw)/s
// =====================================================================
__global__ void __launch_bounds__(256) cap_k3() {
    const int j = blockIdx.x * 256 + threadIdx.x;
    float s0 = 0.f, s1 = 0.f;
#pragma unroll 8
    for (int n = 0; n < N2; n += 2) {
        s0 += __expf(g_raw[(size_t)n * BI + j]);
        s1 += __expf(g_raw[(size_t)(n + 1) * BI + j]);
    }
    const float inv = 1.f / (s0 + s1);
#pragma unroll 8
    for (int n = 0; n < N2; n++) {
        float r = g_raw[(size_t)n * BI + j];
        g_raw[(size_t)n * BI + j] = __expf(r) * inv;
    }
}

// =====================================================================
// K4 partial: part[s][n0+nn][b][d] = sum_{i in slice} c * pred
// c prefetched into smem via TMA alongside W/x (no inline LDG)
// =====================================================================
__global__ void __launch_bounds__(256, 2) cap_k4p(const float* __restrict__ x,
                                                  const float* __restrict__ W) {
    extern __shared__ float sm[];
    __shared__ __align__(8) ull mbars[2];
    const int n0 = blockIdx.x * NW, s = blockIdx.y;
    const int t = threadIdx.x, w = t >> 5, lane = t & 31;
    const int dq = w & 3, ilh = w >> 2;
    const int b0 = lane, b1 = lane + 32;
    const int ib = s * ISL;
    const uint32_t sbase = (uint32_t)__cvta_generic_to_shared(sm);
    const uint32_t mb[2] = { (uint32_t)__cvta_generic_to_shared(&mbars[0]),
                             (uint32_t)__cvta_generic_to_shared(&mbars[1]) };

    if (t == 0) { mbar_init(mb[0], 8); mbar_init(mb[1], 8); }
    __syncthreads();

    ull accA[NW][4], accB[NW][4];
#pragma unroll
    for (int nn = 0; nn < NW; nn++)
#pragma unroll
        for (int e = 0; e < 4; e++) { accA[nn][e] = 0ULL; accB[nn][e] = 0ULL; }

    tile_load_c(sbase, mb[0], x, W, n0, ib, t);

    for (int tt = 0; tt < TILES; tt++) {
        mbar_wait(mb[tt & 1], (tt >> 1) & 1);
        __syncthreads();
        if (tt + 1 < TILES)
            tile_load_c(sbase + ((tt + 1) & 1) * STAGE4_F * 4, mb[(tt + 1) & 1],
                        x, W, n0, ib + (tt + 1) * IL, t);

        const float* wsb = sm + (tt & 1) * STAGE4_F;
        const float* xsb = wsb + WS_F;
        const float* csb = xsb + XS_F;         // [nn][il][b]
#pragma unroll
        for (int ii = 0; ii < 4; ii++) {
            const int il = ilh * 4 + ii;
            ulonglong2 xA01 = *(const ulonglong2*)&xsb[b0 * XROW + il * 8];
            ulonglong2 xA23 = *(const ulonglong2*)&xsb[b0 * XROW + il * 8 + 4];
            ulonglong2 xB01 = *(const ulonglong2*)&xsb[b1 * XROW + il * 8];
            ulonglong2 xB23 = *(const ulonglong2*)&xsb[b1 * XROW + il * 8 + 4];
#pragma unroll
            for (int nn = 0; nn < NW; nn++) {
                float cA = csb[nn * 512 + il * BATCH + b0];
                float cB = csb[nn * 512 + il * BATCH + b1];
                ull c2A = pack2(cA, cA);
                ull c2B = pack2(cB, cB);
                ull xa0 = fmul2(c2A, xA01.x), xa1 = fmul2(c2A, xA01.y);
                ull xa2 = fmul2(c2A, xA23.x), xa3 = fmul2(c2A, xA23.y);
                ull xb0 = fmul2(c2B, xB01.x), xb1 = fmul2(c2B, xB01.y);
                ull xb2 = fmul2(c2B, xB23.x), xb3 = fmul2(c2B, xB23.y);
                const ulonglong2* wv =
                    (const ulonglong2*)&wsb[(il * NW + nn) * 128 + dq * 32];
#pragma unroll
                for (int e = 0; e < 4; e++) {
                    ulonglong2 w01 = wv[2 * e], w23 = wv[2 * e + 1];
                    accA[nn][e] = ffma2(w01.x, xa0, accA[nn][e]);
                    accA[nn][e] = ffma2(w01.y, xa1, accA[nn][e]);
                    accA[nn][e] = ffma2(w23.x, xa2, accA[nn][e]);
                    accA[nn][e] = ffma2(w23.y, xa3, accA[nn][e]);
                    accB[nn][e] = ffma2(w01.x, xb0, accB[nn][e]);
                    accB[nn][e] = ffma2(w01.y, xb1, accB[nn][e]);
                    accB[nn][e] = ffma2(w23.x, xb2, accB[nn][e]);
                    accB[nn][e] = ffma2(w23.y, xb3, accB[nn][e]);
                }
            }
        }
    }

    __syncthreads();
    float* red = sm;
#pragma unroll
    for (int nn = 0; nn < NW; nn++)
#pragma unroll
        for (int e = 0; e < 4; e++) {
            red[w * 1024 + b0 * 16 + nn * 4 + e] = hadd2(accA[nn][e]);
            red[w * 1024 + b1 * 16 + nn * 4 + e] = hadd2(accB[nn][e]);
        }
    __syncthreads();
    {
        int bb = t >> 2, q = t & 3;
#pragma unroll
        for (int nn = 0; nn < NW; nn++) {
            float v[4];
#pragma unroll
            for (int e = 0; e < 4; e++)
                v[e] = red[(0 * 4 + q) * 1024 + bb * 16 + nn * 4 + e]
                     + red[(1 * 4 + q) * 1024 + bb * 16 + nn * 4 + e];
            *(float4*)&g_part[(((size_t)s * N2 + n0 + nn) * BATCH + bb) * DDIM + q * 4] =
                make_float4(v[0], v[1], v[2], v[3]);
        }
    }
}

// =====================================================================
// K4 reduce: out[b][n][d] = squash_d( sum_s part[s][n][b][d] )
// =====================================================================
__global__ void __launch_bounds__(64) cap_k4r(float* __restrict__ out) {
    const int n = blockIdx.x, b = threadIdx.x;
    float sv[16];
#pragma unroll
    for (int d = 0; d < 16; d++) sv[d] = 0.f;
    for (int sl = 0; sl < SLICES; sl++) {
        const float4* p = (const float4*)&g_part[(((size_t)sl * N2 + n) * BATCH + b) * DDIM];
#pragma unroll
        for (int q = 0; q < 4; q++) {
            float4 v = p[q];
            sv[4 * q + 0] += v.x; sv[4 * q + 1] += v.y;
            sv[4 * q + 2] += v.z; sv[4 * q + 3] += v.w;
        }
    }
    float sq = 0.f;
#pragma unroll
    for (int d = 0; d < 16; d++) sq += sv[d] * sv[d];
    float f = sq / ((1.f + sq) * sqrtf(sq + EPSF));
    float4* o = (float4*)&out[((size_t)b * N2 + n) * DDIM];
#pragma unroll
    for (int q = 0; q < 4; q++)
        o[q] = make_float4(f * sv[4 * q], f * sv[4 * q + 1],
                           f * sv[4 * q + 2], f * sv[4 * q + 3]);
}

// =====================================================================
extern "C" void kernel_launch(void* const* d_in, const int* in_sizes, int n_in,
                              void* d_out, int out_size) {
    const float* x = (const float*)d_in[0];
    const float* W = (const float*)d_in[1];
    if (n_in >= 2 && in_sizes[0] > in_sizes[1]) {
        const float* tmp = x; x = W; W = tmp;
    }
    float* out = (float*)d_out;

    cudaFuncSetAttribute(cap_k1p, cudaFuncAttributeMaxDynamicSharedMemorySize, SM_MAIN);
    cudaFuncSetAttribute(cap_k2,  cudaFuncAttributeMaxDynamicSharedMemorySize, SM_K2);
    cudaFuncSetAttribute(cap_k4p, cudaFuncAttributeMaxDynamicSharedMemorySize, SM_K4);

    dim3 g(NBLK, SLICES);
    cap_k1p<<<g, 256, SM_MAIN>>>(x, W);
    cap_k2 <<<g, 256, SM_K2 >>>(x, W);
    cap_k3 <<<BI / 256, 256>>>();
    cap_k4p<<<g, 256, SM_K4>>>(x, W);
    cap_k4r<<<N2, 64>>>(out);
}